// round 5
// baseline (speedup 1.0000x reference)
#include <cuda_runtime.h>
#include <math.h>

#define BB 16
#define TT 32

__constant__ float c_anch[18] = {
    10.f/8.f, 13.f/8.f, 16.f/8.f, 30.f/8.f, 33.f/8.f, 23.f/8.f,
    30.f/16.f, 61.f/16.f, 62.f/16.f, 45.f/16.f, 59.f/16.f, 119.f/16.f,
    116.f/32.f, 90.f/32.f, 156.f/32.f, 198.f/32.f, 373.f/32.f, 326.f/32.f
};

// Dense geometry (runs of 5 contiguous channels per (b,anchor), run=b*3+a):
//   scale0: 48 runs x 8000 f4 -> 2 blocks/run -> blocks [0,96),   4000 f4 each
//   scale1: 48 runs x 2000 f4 -> 2 runs/block -> blocks [96,120), 4000 f4 each
//   scale2: 48 runs x  500 f4 -> 8 runs/block -> blocks [120,126),4000 f4 each
// 126 blocks x 512 threads, 8 front-batched float4 loads per thread.
// Blocks [0,48) additionally run one corr unit (scale = bid>>4, batch = bid&15).
#define NBLK 126

// accumulators per scale: [0]=box_base [1]=sp_base [2]=box_delta
//                         [3]=obj_sum [4]=noobj_sub [5]=cls_sum [6]=n_obj
// zero at init; reset to zero by the last block of every replay.
__device__ float g_acc[3][7];
__device__ int   g_ticket;

__device__ __forceinline__ float sp(float x) {
    // softplus = max(x,0) + log1p(exp(-|x|)); 2-MUFU form
    const float z = exp2f(-1.44269504f * fabsf(x));
    return fmaxf(x, 0.f) + 0.69314718f * __log2f(1.f + z);
}

__device__ __forceinline__ float warp_sum(float v) {
    #pragma unroll
    for (int o = 16; o; o >>= 1) v += __shfl_down_sync(0xffffffffu, v, o);
    return v;
}

__global__ void __launch_bounds__(512)
fused_kernel(const float* __restrict__ p0,
             const float* __restrict__ p1,
             const float* __restrict__ p2,
             const float* __restrict__ targets,
             float* __restrict__ out) {
    const int bid = blockIdx.x, tid = threadIdx.x;
    const int lane = tid & 31, w = tid >> 5;

    __shared__ int   s_lin[512];
    __shared__ int   s_val[512];
    __shared__ int   s_ok[512];
    __shared__ int   s_meta[512];
    __shared__ float s_tb[512][4];
    __shared__ float red[16][5];

    // ---------------- dense base pass: 8 independent LDG.128 ----------------
    float4 v[8];
    bool isbox[8];
    const float4 z4 = make_float4(0.f, 0.f, 0.f, 0.f);
    int dsc;   // scale of this dense block

    if (bid < 96) {
        dsc = 0;
        const int run = bid >> 1, h = bid & 1;
        const float4* b4 = reinterpret_cast<const float4*>(p0)
                         + run * 40000 + h * 4000;
        #pragma unroll
        for (int k = 0; k < 8; k++) {
            const int i = k * 512 + tid;
            const bool ok = i < 4000;
            v[k] = ok ? b4[i] : z4;
            isbox[k] = (!ok) || (h == 0) || (i < 2400);  // global f<6400 -> box
        }
    } else if (bid < 120) {
        dsc = 1;
        const int j = bid - 96;
        const float4* b4 = reinterpret_cast<const float4*>(p1) + j * 20000;
        #pragma unroll
        for (int k = 0; k < 8; k++) {
            const int i = k * 512 + tid;
            const bool ok = i < 4000;
            const int r = (i >= 2000) ? 1 : 0;
            const int off = i - 2000 * r;
            v[k] = ok ? b4[r * 10000 + off] : z4;
            isbox[k] = (!ok) || (off < 1600);
        }
    } else {
        dsc = 2;
        const int j = bid - 120;
        const float4* b4 = reinterpret_cast<const float4*>(p2) + j * 20000;
        #pragma unroll
        for (int k = 0; k < 8; k++) {
            const int i = k * 512 + tid;
            const bool ok = i < 4000;
            const int r = i / 500;           // constant divisor
            const int off = i - 500 * r;
            v[k] = ok ? b4[r * 2500 + off] : z4;
            isbox[k] = (!ok) || (off < 400);
        }
    }

    float bacc = 0.f, sacc = 0.f;
    #pragma unroll
    for (int k = 0; k < 8; k++) {
        if (isbox[k]) {
            bacc += v[k].x * v[k].x + v[k].y * v[k].y
                  + v[k].z * v[k].z + v[k].w * v[k].w;
        } else {
            sacc += sp(v[k].x) + sp(v[k].y) + sp(v[k].z) + sp(v[k].w);
        }
    }

    bacc = warp_sum(bacc); sacc = warp_sum(sacc);
    if (lane == 0) { red[w][0] = bacc; red[w][1] = sacc; }
    __syncthreads();
    if (tid == 0) {
        float b2 = 0.f, s2 = 0.f;
        #pragma unroll
        for (int i = 0; i < 16; i++) { b2 += red[i][0]; s2 += red[i][1]; }
        atomicAdd(&g_acc[dsc][0], b2);
        atomicAdd(&g_acc[dsc][1], s2);
    }
    __syncthreads();   // red[] reused by corr below

    // ---------------- corr unit (blocks 0..47 only) ----------------
    if (bid < 48) {
        const int s   = bid >> 4;       // scale
        const int blk = bid & 15;       // batch gathered by this block
        const int b = tid >> 5, t = tid & 31;
        const int Wd[3] = {80, 40, 20};
        const int W = Wd[s], HW = W * W;

        const float* tg = targets + (size_t)(b * TT + t) * 5;
        const float cls = tg[0], tx = tg[1], ty = tg[2], tw = tg[3], th = tg[4];

        int gx = (int)floorf(tx * (float)W); gx = min(max(gx, 0), W - 1);
        int gy = (int)floorf(ty * (float)W); gy = min(max(gy, 0), W - 1);

        float best = -1.f; int ba = 0;
        #pragma unroll
        for (int a = 0; a < 3; a++) {
            const float aw = c_anch[s * 6 + a * 2], ah = c_anch[s * 6 + a * 2 + 1];
            const float inter = fminf(tw, aw) * fminf(th, ah);
            const float iou = inter / (tw * th + aw * ah - inter + 1e-6f);
            if (iou > best) { best = iou; ba = a; }   // first-max wins
        }
        const int valid = (best > 0.3f) ? 1 : 0;
        const int lin = (gy * W + gx) * 3 + ba;

        s_lin[tid] = lin;
        s_val[tid] = valid;
        s_meta[tid] = (gy << 16) | (gx << 8) | (ba << 5) | (int)cls;
        {
            const float aw = c_anch[s * 6 + ba * 2], ah = c_anch[s * 6 + ba * 2 + 1];
            s_tb[tid][0] = tx * (float)W - (float)gx;
            s_tb[tid][1] = ty * (float)W - (float)gy;
            s_tb[tid][2] = logf(tw / aw + 1e-6f);
            s_tb[tid][3] = logf(th / ah + 1e-6f);
        }
        __syncthreads();

        int shadowed = 0;
        for (int t2 = t + 1; t2 < TT; t2++) {
            const int i2 = (b << 5) | t2;
            if (s_lin[i2] == lin && s_val[i2]) shadowed = 1;
        }
        s_ok[tid] = valid && !shadowed;
        __syncthreads();

        const float* p = (s == 0) ? p0 : ((s == 1) ? p1 : p2);

        float bd = 0.f, os = 0.f, ns = 0.f, cs = 0.f, nv = 0.f;
        #pragma unroll
        for (int j = 0; j < 2; j++) {
            const int r = (blk << 5) + (w << 1) + j;
            if (s_ok[r]) {
                nv += (lane == 0) ? 1.f : 0.f;
                const int m = s_meta[r];
                const int rgy = m >> 16, rgx = (m >> 8) & 0xff;
                const int rba = (m >> 5) & 3, rcls = m & 31;
                if (lane < 25) {
                    const float x = p[(size_t)(blk * 75 + rba * 25 + lane) * HW
                                      + rgy * W + rgx];
                    if (lane < 4) {
                        const float tb = s_tb[r][lane];
                        bd += tb * tb - 2.f * x * tb;
                    } else if (lane == 4) {
                        os += sp(-x);
                        ns += sp(x);
                    } else {
                        float c = sp(x);
                        if (lane - 5 == rcls) c -= x;
                        cs += c;
                    }
                }
            }
        }
        bd = warp_sum(bd); os = warp_sum(os); ns = warp_sum(ns);
        cs = warp_sum(cs); nv = warp_sum(nv);

        if (lane == 0) {
            red[w][0] = bd; red[w][1] = os; red[w][2] = ns;
            red[w][3] = cs; red[w][4] = nv;
        }
        __syncthreads();
        if (tid == 0) {
            float a0 = 0, a1 = 0, a2 = 0, a3 = 0, a4 = 0;
            #pragma unroll
            for (int i = 0; i < 16; i++) {
                a0 += red[i][0]; a1 += red[i][1]; a2 += red[i][2];
                a3 += red[i][3]; a4 += red[i][4];
            }
            atomicAdd(&g_acc[s][2], a0);
            atomicAdd(&g_acc[s][3], a1);
            atomicAdd(&g_acc[s][4], a2);
            atomicAdd(&g_acc[s][5], a3);
            atomicAdd(&g_acc[s][6], a4);
        }
    }

    // ---------------- last-block finalize ----------------
    __threadfence();
    __shared__ int is_last;
    __syncthreads();
    if (tid == 0) is_last = (atomicAdd(&g_ticket, 1) == NBLK - 1);
    __syncthreads();
    if (!is_last) return;

    if (tid == 0) {
        const int Wd[3] = {80, 40, 20};
        float total = 0.f;
        #pragma unroll
        for (int sc = 0; sc < 3; sc++) {
            const float bb   = g_acc[sc][0];
            const float ss   = g_acc[sc][1];
            const float bdq  = g_acc[sc][2];
            const float osum = g_acc[sc][3];
            const float nsub = g_acc[sc][4];
            const float csum = g_acc[sc][5];
            const float nobj = g_acc[sc][6];
            const float cells = (float)(BB * Wd[sc] * Wd[sc] * 3);
            const float n_obj = nobj + 1e-6f;
            const float n_noobj = (cells - nobj) + 1e-6f;
            const float box_loss   = (bb + bdq) / n_obj;
            const float obj_loss   = osum / n_obj;
            const float noobj_loss = (ss - nsub) / n_noobj;
            const float cls_loss   = csum / n_obj;
            total += 0.05f * box_loss + 1.5f * (obj_loss + 0.5f * noobj_loss)
                   + 0.15f * cls_loss;
        }
        out[0] = total;
        // reset accumulators for the next graph replay (only the last block
        // runs after all adds; next replay starts from zero deterministically)
        #pragma unroll
        for (int sc = 0; sc < 3; sc++)
            #pragma unroll
            for (int q = 0; q < 7; q++) g_acc[sc][q] = 0.f;
        g_ticket = 0;
    }
}

extern "C" void kernel_launch(void* const* d_in, const int* in_sizes, int n_in,
                              void* d_out, int out_size) {
    const float* p0 = (const float*)d_in[0];
    const float* p1 = (const float*)d_in[1];
    const float* p2 = (const float*)d_in[2];
    const float* tg = (const float*)d_in[3];
    float* out = (float*)d_out;

    fused_kernel<<<NBLK, 512>>>(p0, p1, p2, tg, out);
}

// round 6
// speedup vs baseline: 1.0201x; 1.0201x over previous
#include <cuda_runtime.h>
#include <math.h>

#define BB 16
#define TT 32

__constant__ float c_anch[18] = {
    10.f/8.f, 13.f/8.f, 16.f/8.f, 30.f/8.f, 33.f/8.f, 23.f/8.f,
    30.f/16.f, 61.f/16.f, 62.f/16.f, 45.f/16.f, 59.f/16.f, 119.f/16.f,
    116.f/32.f, 90.f/32.f, 156.f/32.f, 198.f/32.f, 373.f/32.f, 326.f/32.f
};

// Dense geometry (runs of 5 contiguous channels per (b,anchor), run=b*3+a):
//   scale0: 48 runs x 8000 f4 -> 2 blocks/run -> blocks [0,96),   4000 f4 each
//   scale1: 48 runs x 2000 f4 -> 2 runs/block -> blocks [96,120), 4000 f4 each
//   scale2: 48 runs x  500 f4 -> 8 runs/block -> blocks [120,126),4000 f4 each
// 126 blocks x 512 threads, 8 front-batched float4 loads per thread.
// Blocks [0,48) additionally run one warp-local corr unit
// (scale = bid>>4, batch = bid&15) fully overlapped with dense load flight.
#define NBLK 126

// accumulators per scale: [0]=box_base [1]=sp_base [2]=box_delta
//                         [3]=obj_sum [4]=noobj_sub [5]=cls_sum [6]=n_obj
// zero at init; reset to zero by the last block of every replay.
__device__ float g_acc[3][7];
__device__ int   g_ticket;

__device__ __forceinline__ float sp(float x) {
    // softplus = max(x,0) + log1p(exp(-|x|)); 2-MUFU form
    const float z = exp2f(-1.44269504f * fabsf(x));
    return fmaxf(x, 0.f) + 0.69314718f * __log2f(1.f + z);
}

__device__ __forceinline__ float warp_sum(float v) {
    #pragma unroll
    for (int o = 16; o; o >>= 1) v += __shfl_down_sync(0xffffffffu, v, o);
    return v;
}

__global__ void __launch_bounds__(512, 1)
fused_kernel(const float* __restrict__ p0,
             const float* __restrict__ p1,
             const float* __restrict__ p2,
             const float* __restrict__ targets,
             float* __restrict__ out) {
    const int bid = blockIdx.x, tid = threadIdx.x;
    const int lane = tid & 31, w = tid >> 5;
    const unsigned FULL = 0xffffffffu;

    __shared__ float red[16][2];

    // ---------------- dense loads: 8 independent LDG.128, issued first ------
    float4 v[8];
    bool isbox[8];
    const float4 z4 = make_float4(0.f, 0.f, 0.f, 0.f);
    int dsc;   // scale of this dense block

    if (bid < 96) {
        dsc = 0;
        const int run = bid >> 1, h = bid & 1;
        const float4* b4 = reinterpret_cast<const float4*>(p0)
                         + run * 40000 + h * 4000;
        #pragma unroll
        for (int k = 0; k < 8; k++) {
            const int i = k * 512 + tid;
            const bool ok = i < 4000;
            v[k] = ok ? b4[i] : z4;
            isbox[k] = (!ok) || (h == 0) || (i < 2400);  // global f<6400 -> box
        }
    } else if (bid < 120) {
        dsc = 1;
        const int j = bid - 96;
        const float4* b4 = reinterpret_cast<const float4*>(p1) + j * 20000;
        #pragma unroll
        for (int k = 0; k < 8; k++) {
            const int i = k * 512 + tid;
            const bool ok = i < 4000;
            const int r = (i >= 2000) ? 1 : 0;
            const int off = i - 2000 * r;
            v[k] = ok ? b4[r * 10000 + off] : z4;
            isbox[k] = (!ok) || (off < 1600);
        }
    } else {
        dsc = 2;
        const int j = bid - 120;
        const float4* b4 = reinterpret_cast<const float4*>(p2) + j * 20000;
        #pragma unroll
        for (int k = 0; k < 8; k++) {
            const int i = k * 512 + tid;
            const bool ok = i < 4000;
            const int r = i / 500;           // constant divisor
            const int off = i - 500 * r;
            v[k] = ok ? b4[r * 2500 + off] : z4;
            isbox[k] = (!ok) || (off < 400);
        }
    }

    // ---------------- corr unit (blocks 0..47): warp-local, overlapped ------
    if (bid < 48) {
        const int s   = bid >> 4;       // scale
        const int blk = bid & 15;       // batch gathered by this block
        const int Wd[3] = {80, 40, 20};
        const int W = Wd[s], HW = W * W;

        // every warp redundantly computes prep for all 32 targets of batch blk
        // (one target per lane), entirely in registers.
        const float* tg = targets + (size_t)(blk * TT + lane) * 5;
        const float cls = tg[0], tx = tg[1], ty = tg[2], tw = tg[3], th = tg[4];

        int gx = (int)floorf(tx * (float)W); gx = min(max(gx, 0), W - 1);
        int gy = (int)floorf(ty * (float)W); gy = min(max(gy, 0), W - 1);

        float best = -1.f; int ba = 0;
        #pragma unroll
        for (int a = 0; a < 3; a++) {
            const float aw = c_anch[s * 6 + a * 2], ah = c_anch[s * 6 + a * 2 + 1];
            const float inter = fminf(tw, aw) * fminf(th, ah);
            const float iou = inter / (tw * th + aw * ah - inter + 1e-6f);
            if (iou > best) { best = iou; ba = a; }   // first-max wins
        }
        const int valid = (best > 0.3f) ? 1 : 0;
        const int lin = (gy * W + gx) * 3 + ba;

        // shadow: any later lane (same batch) with equal lin and valid
        const unsigned match = __match_any_sync(FULL, lin);
        const unsigned vmask = __ballot_sync(FULL, valid != 0);
        const unsigned later = 0xFFFFFFFEu << lane;   // lanes > lane (0 at lane 31)
        const int ok_self = valid && !(match & vmask & later);

        const float aw = c_anch[s * 6 + ba * 2], ah = c_anch[s * 6 + ba * 2 + 1];
        const float tb0 = tx * (float)W - (float)gx;
        const float tb1 = ty * (float)W - (float)gy;
        const float tb2 = __logf(tw / aw + 1e-6f);
        const float tb3 = __logf(th / ah + 1e-6f);
        const int meta = (gy << 16) | (gx << 8) | (ba << 5) | (int)cls;

        const float* p = (s == 0) ? p0 : ((s == 1) ? p1 : p2);

        float bd = 0.f, os = 0.f, ns = 0.f, cs = 0.f, nv = 0.f;
        #pragma unroll
        for (int j = 0; j < 2; j++) {
            const int r = (w << 1) + j;    // record (target index) this warp handles
            const int okr  = __shfl_sync(FULL, ok_self, r);
            const int m    = __shfl_sync(FULL, meta, r);
            const float b0 = __shfl_sync(FULL, tb0, r);
            const float b1 = __shfl_sync(FULL, tb1, r);
            const float b2 = __shfl_sync(FULL, tb2, r);
            const float b3 = __shfl_sync(FULL, tb3, r);
            if (okr) {
                nv += (lane == 0) ? 1.f : 0.f;
                const int rgy = m >> 16, rgx = (m >> 8) & 0xff;
                const int rba = (m >> 5) & 3, rcls = m & 31;
                if (lane < 25) {
                    const float x = p[(size_t)(blk * 75 + rba * 25 + lane) * HW
                                      + rgy * W + rgx];
                    if (lane < 4) {
                        const float tb = (lane == 0) ? b0 :
                                         (lane == 1) ? b1 :
                                         (lane == 2) ? b2 : b3;
                        bd += tb * tb - 2.f * x * tb;
                    } else if (lane == 4) {
                        os += sp(-x);
                        ns += sp(x);
                    } else {
                        float c = sp(x);
                        if (lane - 5 == rcls) c -= x;
                        cs += c;
                    }
                }
            }
        }
        bd = warp_sum(bd); os = warp_sum(os); ns = warp_sum(ns);
        cs = warp_sum(cs); nv = warp_sum(nv);
        if (lane == 0) {
            atomicAdd(&g_acc[s][2], bd);
            atomicAdd(&g_acc[s][3], os);
            atomicAdd(&g_acc[s][4], ns);
            atomicAdd(&g_acc[s][5], cs);
            atomicAdd(&g_acc[s][6], nv);
        }
    }

    // ---------------- dense compute (loads have landed by now) --------------
    float bacc = 0.f, sacc = 0.f;
    #pragma unroll
    for (int k = 0; k < 8; k++) {
        if (isbox[k]) {
            bacc += v[k].x * v[k].x + v[k].y * v[k].y
                  + v[k].z * v[k].z + v[k].w * v[k].w;
        } else {
            sacc += sp(v[k].x) + sp(v[k].y) + sp(v[k].z) + sp(v[k].w);
        }
    }
    bacc = warp_sum(bacc); sacc = warp_sum(sacc);
    if (lane == 0) { red[w][0] = bacc; red[w][1] = sacc; }
    __syncthreads();
    if (tid == 0) {
        float b2 = 0.f, s2 = 0.f;
        #pragma unroll
        for (int i = 0; i < 16; i++) { b2 += red[i][0]; s2 += red[i][1]; }
        atomicAdd(&g_acc[dsc][0], b2);
        atomicAdd(&g_acc[dsc][1], s2);
    }

    // ---------------- last-block finalize ----------------
    __threadfence();
    __shared__ int is_last;
    __syncthreads();
    if (tid == 0) is_last = (atomicAdd(&g_ticket, 1) == NBLK - 1);
    __syncthreads();
    if (!is_last) return;

    if (tid == 0) {
        const int Wd[3] = {80, 40, 20};
        float total = 0.f;
        #pragma unroll
        for (int sc = 0; sc < 3; sc++) {
            const float bb   = g_acc[sc][0];
            const float ss   = g_acc[sc][1];
            const float bdq  = g_acc[sc][2];
            const float osum = g_acc[sc][3];
            const float nsub = g_acc[sc][4];
            const float csum = g_acc[sc][5];
            const float nobj = g_acc[sc][6];
            const float cells = (float)(BB * Wd[sc] * Wd[sc] * 3);
            const float n_obj = nobj + 1e-6f;
            const float n_noobj = (cells - nobj) + 1e-6f;
            const float box_loss   = (bb + bdq) / n_obj;
            const float obj_loss   = osum / n_obj;
            const float noobj_loss = (ss - nsub) / n_noobj;
            const float cls_loss   = csum / n_obj;
            total += 0.05f * box_loss + 1.5f * (obj_loss + 0.5f * noobj_loss)
                   + 0.15f * cls_loss;
        }
        out[0] = total;
        // reset accumulators for the next graph replay
        #pragma unroll
        for (int sc = 0; sc < 3; sc++)
            #pragma unroll
            for (int q = 0; q < 7; q++) g_acc[sc][q] = 0.f;
        g_ticket = 0;
    }
}

extern "C" void kernel_launch(void* const* d_in, const int* in_sizes, int n_in,
                              void* d_out, int out_size) {
    const float* p0 = (const float*)d_in[0];
    const float* p1 = (const float*)d_in[1];
    const float* p2 = (const float*)d_in[2];
    const float* tg = (const float*)d_in[3];
    float* out = (float*)d_out;

    fused_kernel<<<NBLK, 512>>>(p0, p1, p2, tg, out);
}